// round 13
// baseline (speedup 1.0000x reference)
#include <cuda_runtime.h>
#include <math.h>

#define HID   512
#define VOCAB 50000
#define BATCH 64
#define SRC   50
#define STEPS 31
#define VT    128                 /* vocab tile per logits block */
#define NLOG  391                 /* ceil(50000/128) */
#define KT    32                  /* k tile */
#define NTILE (HID / KT)          /* 16 */
#define NEG_INF (-3.402823466e38f)

typedef unsigned long long ull;

// ---------------- persistent device state (no allocations allowed) ----------
__device__ __align__(16) float g_h[BATCH * HID];      // post-attention hidden (carry)
__device__ __align__(16) float g_c[BATCH * HID];      // post-attention cell   (carry)
__device__ __align__(16) float g_hrnn[BATCH * HID];   // raw LSTM outputs this step
__device__ __align__(16) float g_crnn[BATCH * HID];
__device__ int   g_tok[BATCH];
__device__ float g_pmax[NLOG * BATCH];
__device__ int   g_pidx[NLOG * BATCH];
__device__ int   g_done;

// ---------------- f32x2 packed-FMA helpers (Blackwell dual fp32 pipe) -------
__device__ __forceinline__ ull pack2(float x, float y) {
    ull r; asm("mov.b64 %0, {%1,%2};" : "=l"(r) : "f"(x), "f"(y)); return r;
}
__device__ __forceinline__ void unpack2(ull a, float& x, float& y) {
    asm("mov.b64 {%0,%1}, %2;" : "=f"(x), "=f"(y) : "l"(a));
}
__device__ __forceinline__ ull fma2(ull a, ull b, ull c) {
    ull d; asm("fma.rn.f32x2 %0, %1, %2, %3;" : "=l"(d) : "l"(a), "l"(b), "l"(c)); return d;
}
__device__ __forceinline__ float sigmoidf_(float x) { return 1.f / (1.f + expf(-x)); }

// ---------------- init ------------------------------------------------------
__global__ void k_init(const float* __restrict__ h0, const float* __restrict__ c0,
                       const int* __restrict__ t0) {
    int tid = blockIdx.x * blockDim.x + threadIdx.x;
    for (int i = tid; i < BATCH * HID; i += blockDim.x * gridDim.x) {
        g_h[i] = h0[i];
        g_c[i] = c0[i];
    }
    if (tid < BATCH) g_tok[tid] = t0[tid];
    if (tid == 0) g_done = 0;
}

// ---------------- LSTM cell -------------------------------------------------
// grid 128 x 512 threads. Block owns 4 hidden dims across 4 gates = 16 rows.
// Thread: 1 gate row x 2 batches (one f32x2 acc). Weights splatted in smem
// (tiny), x/h natural batch-pairs (broadcast reads). Register prefetch.
__global__ void __launch_bounds__(512) k_lstm(const float* __restrict__ embed,
                       const float* __restrict__ w_ih,
                       const float* __restrict__ w_hh,
                       const float* __restrict__ b_ih,
                       const float* __restrict__ b_hh) {
    __shared__ ull   wi_d[KT][16];     // splatted, 4KB
    __shared__ ull   wh_d[KT][16];     // 4KB
    __shared__ float x_sm[KT][64];     // 8KB
    __shared__ float hs_sm[KT][64];    // 8KB
    __shared__ float gate_sm[16][66];  // padded rows (bank-spread)
    __shared__ int   tok_sm[BATCH];

    const int tid = threadIdx.x;
    const int hd0 = blockIdx.x * 4;
    if (tid < BATCH) tok_sm[tid] = g_tok[tid];

    // compute roles: rr = gate row (g*4 + dloc), bq = batch pair
    const int rr = tid & 15;
    const int bq = tid >> 4;            // 0..31
    const int jrow = (rr >> 2) * HID + hd0 + (rr & 3);
    const float bias = b_ih[jrow] + b_hh[jrow];
    ull acc = pack2(bias, bias);

    // fill roles
    const int w_rr = tid & 15;
    const int w_kp = (tid >> 4) & 15;   // 16 k-pairs
    const int w_m  = tid >> 8;          // 0: wi, 1: wh
    const int w_j  = (w_rr >> 2) * HID + hd0 + (w_rr & 3);
    const float* wsrc = (w_m ? w_hh : w_ih) + (size_t)w_j * HID;
    const int f_b  = tid & 63;
    const int f_kq = tid >> 6;          // 8 groups of 4 k
    __syncthreads();                    // tok_sm visible

    // prefetch tile 0
    float2 wp = *(const float2*)(wsrc + 2 * w_kp);
    float4 xp = *(const float4*)(embed + (size_t)tok_sm[f_b] * HID + 4 * f_kq);
    float4 hp = *(const float4*)(g_h   + (size_t)f_b        * HID + 4 * f_kq);

    for (int kt = 0; kt < NTILE; kt++) {
        __syncthreads();                // previous compute done reading smem
        {
            ull* wdst = w_m ? &wh_d[0][0] : &wi_d[0][0];
            wdst[(2 * w_kp)     * 16 + w_rr] = pack2(wp.x, wp.x);
            wdst[(2 * w_kp + 1) * 16 + w_rr] = pack2(wp.y, wp.y);
            x_sm [4 * f_kq + 0][f_b] = xp.x;  x_sm [4 * f_kq + 1][f_b] = xp.y;
            x_sm [4 * f_kq + 2][f_b] = xp.z;  x_sm [4 * f_kq + 3][f_b] = xp.w;
            hs_sm[4 * f_kq + 0][f_b] = hp.x;  hs_sm[4 * f_kq + 1][f_b] = hp.y;
            hs_sm[4 * f_kq + 2][f_b] = hp.z;  hs_sm[4 * f_kq + 3][f_b] = hp.w;
        }
        __syncthreads();
        if (kt + 1 < NTILE) {           // prefetch next tile (overlaps compute)
            const int k0n = (kt + 1) * KT;
            wp = *(const float2*)(wsrc + k0n + 2 * w_kp);
            xp = *(const float4*)(embed + (size_t)tok_sm[f_b] * HID + k0n + 4 * f_kq);
            hp = *(const float4*)(g_h   + (size_t)f_b        * HID + k0n + 4 * f_kq);
        }
#pragma unroll 8
        for (int k = 0; k < KT; k++) {
            ull wi = wi_d[k][rr];
            ull wh = wh_d[k][rr];
            ull xv = *(const ull*)&x_sm [k][2 * bq];
            ull hv = *(const ull*)&hs_sm[k][2 * bq];
            acc = fma2(wi, xv, acc);
            acc = fma2(wh, hv, acc);
        }
    }
    *(ull*)&gate_sm[rr][2 * bq] = acc;
    __syncthreads();
    // cell update: 4 hidden dims x 64 batches (gate order i,f,g,o)
    if (tid < 256) {
        int dd = tid >> 6, b = tid & 63;
        float ig = sigmoidf_(gate_sm[dd][b]);
        float fg = sigmoidf_(gate_sm[4 + dd][b]);
        float gg = tanhf(gate_sm[8 + dd][b]);
        float og = sigmoidf_(gate_sm[12 + dd][b]);
        int idx = b * HID + hd0 + dd;
        float cn = fg * g_c[idx] + ig * gg;
        g_crnn[idx] = cn;
        g_hrnn[idx] = og * tanhf(cn);
    }
}

// ---------------- fused: logits(+argmax partials) | attention | final argmax
// Logits: acc = (v, v+1) vocab-pairs per batch -> e tiles natural (no dup),
// only the tiny h tile splatted. Register-prefetched fills.
struct SmLogits { ull e[KT][64]; ull h[KT][64]; };         // 16KB + 16KB
struct SmAttn   { float vv[HID]; float sc[64]; float isum; };
struct SmAmax   { float sv[256]; int si[256]; };
union SmU { SmLogits l; SmAttn a; SmAmax m; };

__global__ void __launch_bounds__(256) k_fused(
        const float* __restrict__ embed, const float* __restrict__ fc_bias,
        const float* __restrict__ enc, float* __restrict__ out_step,
        float* __restrict__ out_tok, int step, int write_tok) {
    __shared__ SmU sm;
    __shared__ int s_last;

    const int tid  = threadIdx.x;
    const int lane = tid & 31;
    const int warp = tid >> 5;
    const int bid  = blockIdx.x;

    if (bid < NLOG) {
        // ================= logits block: 128 vocab x 64 batch =================
        const int vbase = bid * VT;
        const int vpg = lane & 15;          // 16 vp-groups of 4 vocab-pairs
        const int bg  = lane >> 4;          // 2 batch-groups of 4
        const int v0  = vbase + 8 * vpg;    // first vocab row of this thread
        const int bb0 = 8 * warp + 4 * bg;  // first batch of this thread
        const int gval = (v0 + 8 <= VOCAB); // whole 8-v granule valid (VOCAB%8==0)

        ull acc[4][4];                      // [j: vocab pair][b]
#pragma unroll
        for (int j = 0; j < 4; j++) {
            ull bz = 0ull;
            if (gval) { float2 f = *(const float2*)(fc_bias + v0 + 2 * j); bz = pack2(f.x, f.y); }
#pragma unroll
            for (int b = 0; b < 4; b++) acc[j][b] = bz;
        }

        // fill roles
        const int fv  = tid & 127;          // vocab row within tile
        const int fkh = tid >> 7;           // 0/1: which 16-k half
        const int gv  = vbase + fv;
        const int fb  = tid & 63;           // batch
        const int fkq = tid >> 6;           // 0..3: 8-k group

        // prefetch tile 0
        float4 ep[4]; float4 hq[2];
        if (gv < VOCAB) {
            const float4* src = (const float4*)(embed + (size_t)gv * HID + fkh * 16);
#pragma unroll
            for (int jj = 0; jj < 4; jj++) ep[jj] = src[jj];
        } else {
#pragma unroll
            for (int jj = 0; jj < 4; jj++) ep[jj] = make_float4(0.f, 0.f, 0.f, 0.f);
        }
        {
            const float4* hsrc = (const float4*)(g_hrnn + (size_t)fb * HID + fkq * 8);
            hq[0] = hsrc[0]; hq[1] = hsrc[1];
        }

        for (int kt = 0; kt < NTILE; kt++) {
            __syncthreads();
            {   // e: natural (v, v+1) pairs, [k][vp]
                float* ef = (float*)&sm.l.e[0][0];  // [k][vp][half]
                const int vp = fv >> 1, half = fv & 1;
#pragma unroll
                for (int jj = 0; jj < 4; jj++) {
                    float4 f = ep[jj];
                    int kk = fkh * 16 + 4 * jj;
                    ef[((kk + 0) * 64 + vp) * 2 + half] = f.x;
                    ef[((kk + 1) * 64 + vp) * 2 + half] = f.y;
                    ef[((kk + 2) * 64 + vp) * 2 + half] = f.z;
                    ef[((kk + 3) * 64 + vp) * 2 + half] = f.w;
                }
            }
            {   // h: splatted [k][b]
#pragma unroll
                for (int jj = 0; jj < 2; jj++) {
                    float4 f = hq[jj];
                    int kk = fkq * 8 + 4 * jj;
                    sm.l.h[kk + 0][fb] = pack2(f.x, f.x);
                    sm.l.h[kk + 1][fb] = pack2(f.y, f.y);
                    sm.l.h[kk + 2][fb] = pack2(f.z, f.z);
                    sm.l.h[kk + 3][fb] = pack2(f.w, f.w);
                }
            }
            __syncthreads();
            if (kt + 1 < NTILE) {          // prefetch next tile
                const int k0n = (kt + 1) * KT;
                if (gv < VOCAB) {
                    const float4* src = (const float4*)(embed + (size_t)gv * HID + k0n + fkh * 16);
#pragma unroll
                    for (int jj = 0; jj < 4; jj++) ep[jj] = src[jj];
                }
                const float4* hsrc = (const float4*)(g_hrnn + (size_t)fb * HID + k0n + fkq * 8);
                hq[0] = hsrc[0]; hq[1] = hsrc[1];
            }
#pragma unroll 8
            for (int k = 0; k < KT; k++) {
                ulonglong2 eA = *(const ulonglong2*)&sm.l.e[k][4 * vpg];
                ulonglong2 eB = *(const ulonglong2*)&sm.l.e[k][4 * vpg + 2];
                ulonglong2 hA = *(const ulonglong2*)&sm.l.h[k][bb0];
                ulonglong2 hB = *(const ulonglong2*)&sm.l.h[k][bb0 + 2];
                acc[0][0] = fma2(eA.x, hA.x, acc[0][0]); acc[0][1] = fma2(eA.x, hA.y, acc[0][1]);
                acc[0][2] = fma2(eA.x, hB.x, acc[0][2]); acc[0][3] = fma2(eA.x, hB.y, acc[0][3]);
                acc[1][0] = fma2(eA.y, hA.x, acc[1][0]); acc[1][1] = fma2(eA.y, hA.y, acc[1][1]);
                acc[1][2] = fma2(eA.y, hB.x, acc[1][2]); acc[1][3] = fma2(eA.y, hB.y, acc[1][3]);
                acc[2][0] = fma2(eB.x, hA.x, acc[2][0]); acc[2][1] = fma2(eB.x, hA.y, acc[2][1]);
                acc[2][2] = fma2(eB.x, hB.x, acc[2][2]); acc[2][3] = fma2(eB.x, hB.y, acc[2][3]);
                acc[3][0] = fma2(eB.y, hA.x, acc[3][0]); acc[3][1] = fma2(eB.y, hA.y, acc[3][1]);
                acc[3][2] = fma2(eB.y, hB.x, acc[3][2]); acc[3][3] = fma2(eB.y, hB.y, acc[3][3]);
            }
        }

        // epilogue: store logits + per-batch argmax candidates (v ascending)
        float pv[4]; int pi[4];
#pragma unroll
        for (int b = 0; b < 4; b++) {
            const int batch = bb0 + b;
            if (gval) {
                ulonglong2 s0; s0.x = acc[0][b]; s0.y = acc[1][b];
                ulonglong2 s1; s1.x = acc[2][b]; s1.y = acc[3][b];
                *(ulonglong2*)&out_step[(size_t)batch * VOCAB + v0]     = s0;
                *(ulonglong2*)&out_step[(size_t)batch * VOCAB + v0 + 4] = s1;
            }
            float bv = NEG_INF; int bx = 0x7fffffff;
            if (gval) {
#pragma unroll
                for (int j = 0; j < 4; j++) {
                    float lx, ly; unpack2(acc[j][b], lx, ly);
                    int v = v0 + 2 * j;
                    if (lx > bv) { bv = lx; bx = v; }
                    if (ly > bv) { bv = ly; bx = v + 1; }
                }
            }
            pv[b] = bv; pi[b] = bx;
        }
        // reduce over the 16 vpg lanes (offsets < 16 keep bg halves separate)
#pragma unroll
        for (int b = 0; b < 4; b++) {
            float v = pv[b]; int ix = pi[b];
#pragma unroll
            for (int off = 8; off > 0; off >>= 1) {
                float ov = __shfl_xor_sync(0xffffffffu, v, off);
                int   oi = __shfl_xor_sync(0xffffffffu, ix, off);
                if (ov > v || (ov == v && oi < ix)) { v = ov; ix = oi; }
            }
            if (vpg == 0) {
                g_pmax[bid * 64 + bb0 + b] = v;
                g_pidx[bid * 64 + bb0 + b] = ix;
            }
        }
    } else {
        // ================= attention block (h or c) ===========================
        const int a     = bid - NLOG;
        const int bi    = a & 63;
        const int which = a >> 6;
        const float* vr = (which ? g_crnn : g_hrnn) + (size_t)bi * HID;
        for (int d = tid; d < HID; d += 256) sm.a.vv[d] = vr[d];
        __syncthreads();
        for (int s = warp; s < SRC; s += 8) {
            float acc = 0.f;
            const float* er = enc + ((size_t)s * BATCH + bi) * HID;
            for (int d = lane; d < HID; d += 32) acc += er[d] * sm.a.vv[d];
#pragma unroll
            for (int o = 16; o > 0; o >>= 1) acc += __shfl_xor_sync(0xffffffffu, acc, o);
            if (lane == 0) sm.a.sc[s] = acc * 0.04419417382415922f; // 1/sqrt(512)
        }
        __syncthreads();
        if (tid == 0) {
            float m = sm.a.sc[0];
            for (int s = 1; s < SRC; s++) m = fmaxf(m, sm.a.sc[s]);
            float sum = 0.f;
            for (int s = 0; s < SRC; s++) { float e = expf(sm.a.sc[s] - m); sm.a.sc[s] = e; sum += e; }
            sm.a.isum = 1.f / sum;
        }
        __syncthreads();
        const float isum = sm.a.isum;
        float* dst = (which ? g_c : g_h) + (size_t)bi * HID;
        for (int d = tid; d < HID; d += 256) {
            float acc = 0.f;
#pragma unroll 10
            for (int s = 0; s < SRC; s++) acc += sm.a.sc[s] * enc[((size_t)s * BATCH + bi) * HID + d];
            dst[d] = acc * isum + sm.a.vv[d];
        }
    }

    // ================= last-block-done final argmax ===========================
    __threadfence();
    __syncthreads();
    if (tid == 0) {
        int old = atomicAdd(&g_done, 1);
        s_last = (old == (int)gridDim.x - 1);
    }
    __syncthreads();
    if (s_last) {
        const int b = tid & 63, grp = tid >> 6;
        float bv = NEG_INF; int bx = 0x7fffffff;
        for (int p = grp; p < NLOG; p += 4) {
            float v = g_pmax[p * 64 + b];
            int  ix = g_pidx[p * 64 + b];
            if (v > bv || (v == bv && ix < bx)) { bv = v; bx = ix; }
        }
        __syncthreads();   // all threads past union reuse of sm before writing sm.m
        sm.m.sv[tid] = bv; sm.m.si[tid] = bx;
        __syncthreads();
        if (tid < 64) {
            for (int g = 1; g < 4; g++) {
                float v = sm.m.sv[tid + 64 * g];
                int  ix = sm.m.si[tid + 64 * g];
                if (v > bv || (v == bv && ix < bx)) { bv = v; bx = ix; }
            }
            g_tok[b] = bx;
            if (write_tok) out_tok[b * STEPS + step] = (float)bx;
        }
        if (tid == 0) g_done = 0;
    }
}

// ---------------- launch: 1 init + 31 x (lstm, fused) -----------------------
extern "C" void kernel_launch(void* const* d_in, const int* in_sizes, int n_in,
                              void* d_out, int out_size) {
    const float* embed   = (const float*)d_in[0];
    const float* fc_bias = (const float*)d_in[1];
    const float* w_ih    = (const float*)d_in[2];
    const float* w_hh    = (const float*)d_in[3];
    const float* b_ih    = (const float*)d_in[4];
    const float* b_hh    = (const float*)d_in[5];
    const float* enc     = (const float*)d_in[6];
    const float* h0      = (const float*)d_in[7];
    const float* c0      = (const float*)d_in[8];
    const int*   t0      = (const int*)d_in[9];
    float* out = (float*)d_out;

    const long long LT = (long long)STEPS * BATCH * VOCAB;  // 99,200,000
    int write_tok = ((long long)out_size >= LT + (long long)BATCH * STEPS) ? 1 : 0;
    float* out_tok = out + LT;

    k_init<<<32, 256>>>(h0, c0, t0);
    for (int t = 0; t < STEPS; t++) {
        k_lstm<<<128, 512>>>(embed, w_ih, w_hh, b_ih, b_hh);
        k_fused<<<NLOG + 128, 256>>>(embed, fc_bias, enc,
                                     out + (long long)t * BATCH * VOCAB,
                                     out_tok, t, write_tok);
    }
}

// round 14
// speedup vs baseline: 1.3228x; 1.3228x over previous
#include <cuda_runtime.h>
#include <math.h>

#define HID   512
#define VOCAB 50000
#define BATCH 64
#define SRC   50
#define STEPS 31
#define VT    128                 /* vocab tile per logits block */
#define NLOG  391                 /* ceil(50000/128) */
#define KT    32                  /* k tile */
#define NTILE (HID / KT)          /* 16 */
#define NEG_INF (-3.402823466e38f)

typedef unsigned long long ull;

// ---------------- persistent device state (no allocations allowed) ----------
__device__ __align__(16) float g_h[BATCH * HID];      // post-attention hidden (carry)
__device__ __align__(16) float g_c[BATCH * HID];      // post-attention cell   (carry)
__device__ __align__(16) float g_hrnn[BATCH * HID];   // raw LSTM outputs this step
__device__ __align__(16) float g_crnn[BATCH * HID];
__device__ int   g_tok[BATCH];
__device__ float g_pmax[NLOG * BATCH];
__device__ int   g_pidx[NLOG * BATCH];
__device__ int   g_done;

// ---------------- f32x2 packed-FMA helpers (Blackwell dual fp32 pipe) -------
__device__ __forceinline__ ull pack2(float x, float y) {
    ull r; asm("mov.b64 %0, {%1,%2};" : "=l"(r) : "f"(x), "f"(y)); return r;
}
__device__ __forceinline__ void unpack2(ull a, float& x, float& y) {
    asm("mov.b64 {%0,%1}, %2;" : "=f"(x), "=f"(y) : "l"(a));
}
__device__ __forceinline__ ull fma2(ull a, ull b, ull c) {
    ull d; asm("fma.rn.f32x2 %0, %1, %2, %3;" : "=l"(d) : "l"(a), "l"(b), "l"(c)); return d;
}
__device__ __forceinline__ float sigmoidf_(float x) { return 1.f / (1.f + expf(-x)); }

// ---------------- init ------------------------------------------------------
__global__ void k_init(const float* __restrict__ h0, const float* __restrict__ c0,
                       const int* __restrict__ t0) {
    int tid = blockIdx.x * blockDim.x + threadIdx.x;
    for (int i = tid; i < BATCH * HID; i += blockDim.x * gridDim.x) {
        g_h[i] = h0[i];
        g_c[i] = c0[i];
    }
    if (tid < BATCH) g_tok[tid] = t0[tid];
    if (tid == 0) g_done = 0;
}

// ---------------- LSTM cell -------------------------------------------------
// grid 128 x 512 threads. Block = 4 hidden dims x 4 gates = 16 gate rows,
// thread = (row, batch-pair). Smem laid out k-contiguous so ONE LDS.128 feeds
// 2 k-steps: 4 LDS.128 + 4 FFMA2 per 2k (LDS:FMA 1:1, was 2:1).
// Accumulation order per thread unchanged (k ascending, wi then wh).
__global__ void __launch_bounds__(512) k_lstm(const float* __restrict__ embed,
                       const float* __restrict__ w_ih,
                       const float* __restrict__ w_hh,
                       const float* __restrict__ b_ih,
                       const float* __restrict__ b_hh) {
    __shared__ ull   wi_t[16][KT + 2];   // [row][k] splatted pairs, stride 34 ull
    __shared__ ull   wh_t[16][KT + 2];
    __shared__ ull   x_p [32][KT + 2];   // [bpair][k] (x[2bp][k], x[2bp+1][k])
    __shared__ ull   h_p [32][KT + 2];
    __shared__ float gate_sm[16][66];
    __shared__ int   tok_sm[BATCH];

    const int tid = threadIdx.x;
    const int hd0 = blockIdx.x * 4;
    if (tid < BATCH) tok_sm[tid] = g_tok[tid];

    // compute roles
    const int rr = tid & 15;            // gate row: g*4 + dloc
    const int bq = tid >> 4;            // 0..31 batch pair
    const int jrow = (rr >> 2) * HID + hd0 + (rr & 3);
    const float bias = b_ih[jrow] + b_hh[jrow];
    ull acc = pack2(bias, bias);

    // fill roles: threads 0-255 do (wi, x), 256-511 do (wh, h)
    const int w_kp = tid & 15;          // 16 k-pairs (coalesced along k)
    const int w_rr = (tid >> 4) & 15;
    const int w_m  = tid >> 8;
    const int w_j  = (w_rr >> 2) * HID + hd0 + (w_rr & 3);
    const float* wsrc = (w_m ? w_hh : w_ih) + (size_t)w_j * HID;
    const int f_bp = tid & 31;          // batch pair
    const int f_kq = (tid >> 5) & 7;    // 8 groups of 4 k
    __syncthreads();                    // tok_sm visible

    const float *s0, *s1;
    if (w_m) { s0 = g_h + (size_t)(2 * f_bp) * HID;
               s1 = g_h + (size_t)(2 * f_bp + 1) * HID; }
    else     { s0 = embed + (size_t)tok_sm[2 * f_bp]     * HID;
               s1 = embed + (size_t)tok_sm[2 * f_bp + 1] * HID; }

    // prefetch tile 0
    float2 wp = *(const float2*)(wsrc + 2 * w_kp);
    float4 pa = *(const float4*)(s0 + 4 * f_kq);
    float4 pb = *(const float4*)(s1 + 4 * f_kq);

    for (int kt = 0; kt < NTILE; kt++) {
        __syncthreads();                // previous compute done reading smem
        {   // weight store: splatted pairs, 16B aligned (even indices)
            ull* wt = (w_m ? &wh_t[0][0] : &wi_t[0][0]) + w_rr * (KT + 2);
            ulonglong2 wv; wv.x = pack2(wp.x, wp.x); wv.y = pack2(wp.y, wp.y);
            *(ulonglong2*)&wt[2 * w_kp] = wv;
        }
        {   // x/h store: batch-pair packed, k-contiguous
            ull* xt = (w_m ? &h_p[0][0] : &x_p[0][0]) + f_bp * (KT + 2);
            ulonglong2 v0; v0.x = pack2(pa.x, pb.x); v0.y = pack2(pa.y, pb.y);
            ulonglong2 v1; v1.x = pack2(pa.z, pb.z); v1.y = pack2(pa.w, pb.w);
            *(ulonglong2*)&xt[4 * f_kq]     = v0;
            *(ulonglong2*)&xt[4 * f_kq + 2] = v1;
        }
        __syncthreads();
        if (kt + 1 < NTILE) {           // prefetch next tile (overlaps compute)
            const int k0n = (kt + 1) * KT;
            wp = *(const float2*)(wsrc + k0n + 2 * w_kp);
            pa = *(const float4*)(s0 + k0n + 4 * f_kq);
            pb = *(const float4*)(s1 + k0n + 4 * f_kq);
        }
#pragma unroll
        for (int k = 0; k < KT; k += 2) {
            ulonglong2 wi2 = *(const ulonglong2*)&wi_t[rr][k];
            ulonglong2 wh2 = *(const ulonglong2*)&wh_t[rr][k];
            ulonglong2 xv2 = *(const ulonglong2*)&x_p[bq][k];
            ulonglong2 hv2 = *(const ulonglong2*)&h_p[bq][k];
            acc = fma2(wi2.x, xv2.x, acc);
            acc = fma2(wh2.x, hv2.x, acc);
            acc = fma2(wi2.y, xv2.y, acc);
            acc = fma2(wh2.y, hv2.y, acc);
        }
    }
    *(ull*)&gate_sm[rr][2 * bq] = acc;
    __syncthreads();
    // cell update: 4 hidden dims x 64 batches (gate order i,f,g,o)
    if (tid < 256) {
        int dd = tid >> 6, b = tid & 63;
        float ig = sigmoidf_(gate_sm[dd][b]);
        float fg = sigmoidf_(gate_sm[4 + dd][b]);
        float gg = tanhf(gate_sm[8 + dd][b]);
        float og = sigmoidf_(gate_sm[12 + dd][b]);
        int idx = b * HID + hd0 + dd;
        float cn = fg * g_c[idx] + ig * gg;
        g_crnn[idx] = cn;
        g_hrnn[idx] = og * tanhf(cn);
    }
}

// ---------------- fused: logits(+argmax partials) | attention | final argmax
// (exact R11 version: duplicated-e layout, conflict-free 16B/lane reads)
struct SmLogits { ull e[2][KT][64]; float h[KT][64]; };    // 32KB + 8KB
struct SmAttn   { float vv[HID]; float sc[64]; float isum; };
struct SmAmax   { float sv[256]; int si[256]; };
union SmU { SmLogits l; SmAttn a; SmAmax m; };

__global__ void __launch_bounds__(256) k_fused(
        const float* __restrict__ embed, const float* __restrict__ fc_bias,
        const float* __restrict__ enc, float* __restrict__ out_step,
        float* __restrict__ out_tok, int step, int write_tok) {
    __shared__ SmU sm;
    __shared__ int s_last;

    const int tid  = threadIdx.x;
    const int lane = tid & 31;
    const int warp = tid >> 5;
    const int bid  = blockIdx.x;

    if (bid < NLOG) {
        // ================= logits block: 128 vocab x 64 batch =================
        const int vbase = bid * VT;
        const int vL = vbase + 2 * lane;        // iv 0,1
        const int vH = vbase + 64 + 2 * lane;   // iv 2,3

        float bz0 = (vL     < VOCAB) ? fc_bias[vL]     : 0.f;
        float bz1 = (vL + 1 < VOCAB) ? fc_bias[vL + 1] : 0.f;
        float bz2 = (vH     < VOCAB) ? fc_bias[vH]     : 0.f;
        float bz3 = (vH + 1 < VOCAB) ? fc_bias[vH + 1] : 0.f;
        ull acc[4][4];
#pragma unroll
        for (int bp = 0; bp < 4; bp++) {
            acc[0][bp] = pack2(bz0, bz0); acc[1][bp] = pack2(bz1, bz1);
            acc[2][bp] = pack2(bz2, bz2); acc[3][bp] = pack2(bz3, bz3);
        }

        const int fv  = tid & 127;   // fill vocab row
        const int fkh = tid >> 7;    // 0/1: which 16-k half
        const int fb  = tid & 63;    // fill batch
        const int fkq = tid >> 6;    // 0..3: 8-k group

        for (int k0 = 0; k0 < HID; k0 += KT) {
            {   // embed -> dup'd [half][k][v]
                const int gv = vbase + fv;
                ull* dst = &sm.l.e[fv >> 6][fkh * 16][fv & 63];
                if (gv < VOCAB) {
                    const float4* src = (const float4*)(embed + (size_t)gv * HID + k0 + fkh * 16);
#pragma unroll
                    for (int jj = 0; jj < 4; jj++) {
                        float4 f = src[jj];
                        dst[(4 * jj + 0) * 64] = pack2(f.x, f.x);
                        dst[(4 * jj + 1) * 64] = pack2(f.y, f.y);
                        dst[(4 * jj + 2) * 64] = pack2(f.z, f.z);
                        dst[(4 * jj + 3) * 64] = pack2(f.w, f.w);
                    }
                } else {
#pragma unroll
                    for (int jj = 0; jj < 16; jj++) dst[jj * 64] = 0ull;
                }
            }
            {   // h_rnn -> [k][b]
                const float4* hsrc = (const float4*)(g_hrnn + (size_t)fb * HID + k0 + fkq * 8);
                float* hd = &sm.l.h[fkq * 8][fb];
#pragma unroll
                for (int jj = 0; jj < 2; jj++) {
                    float4 f = hsrc[jj];
                    hd[(4 * jj + 0) * 64] = f.x; hd[(4 * jj + 1) * 64] = f.y;
                    hd[(4 * jj + 2) * 64] = f.z; hd[(4 * jj + 3) * 64] = f.w;
                }
            }
            __syncthreads();
#pragma unroll 8
            for (int k = 0; k < KT; k++) {
                ulonglong2 eL = *(const ulonglong2*)&sm.l.e[0][k][2 * lane];
                ulonglong2 eH = *(const ulonglong2*)&sm.l.e[1][k][2 * lane];
                ulonglong2 hA = *(const ulonglong2*)&sm.l.h[k][8 * warp];
                ulonglong2 hB = *(const ulonglong2*)&sm.l.h[k][8 * warp + 4];
                acc[0][0] = fma2(eL.x, hA.x, acc[0][0]); acc[0][1] = fma2(eL.x, hA.y, acc[0][1]);
                acc[0][2] = fma2(eL.x, hB.x, acc[0][2]); acc[0][3] = fma2(eL.x, hB.y, acc[0][3]);
                acc[1][0] = fma2(eL.y, hA.x, acc[1][0]); acc[1][1] = fma2(eL.y, hA.y, acc[1][1]);
                acc[1][2] = fma2(eL.y, hB.x, acc[1][2]); acc[1][3] = fma2(eL.y, hB.y, acc[1][3]);
                acc[2][0] = fma2(eH.x, hA.x, acc[2][0]); acc[2][1] = fma2(eH.x, hA.y, acc[2][1]);
                acc[2][2] = fma2(eH.x, hB.x, acc[2][2]); acc[2][3] = fma2(eH.x, hB.y, acc[2][3]);
                acc[3][0] = fma2(eH.y, hA.x, acc[3][0]); acc[3][1] = fma2(eH.y, hA.y, acc[3][1]);
                acc[3][2] = fma2(eH.y, hB.x, acc[3][2]); acc[3][3] = fma2(eH.y, hB.y, acc[3][3]);
            }
            __syncthreads();
        }

        // epilogue: store logits + per-batch argmax candidates (v ascending)
        float pv[8]; int pi[8];
#pragma unroll
        for (int bp = 0; bp < 4; bp++) {
            float l0e, l0o, l1e, l1o, l2e, l2o, l3e, l3o;
            unpack2(acc[0][bp], l0e, l0o);
            unpack2(acc[1][bp], l1e, l1o);
            unpack2(acc[2][bp], l2e, l2o);
            unpack2(acc[3][bp], l3e, l3o);
            const int be = 8 * warp + 2 * bp, bo = be + 1;
            if (vL < VOCAB) {
                *(float2*)&out_step[(size_t)be * VOCAB + vL] = make_float2(l0e, l1e);
                *(float2*)&out_step[(size_t)bo * VOCAB + vL] = make_float2(l0o, l1o);
            }
            if (vH < VOCAB) {
                *(float2*)&out_step[(size_t)be * VOCAB + vH] = make_float2(l2e, l3e);
                *(float2*)&out_step[(size_t)bo * VOCAB + vH] = make_float2(l2o, l3o);
            }
            float bv = NEG_INF; int bx = 0x7fffffff;
            if (vL < VOCAB) {
                if (l0e > bv) { bv = l0e; bx = vL; }
                if (l1e > bv) { bv = l1e; bx = vL + 1; }
            }
            if (vH < VOCAB) {
                if (l2e > bv) { bv = l2e; bx = vH; }
                if (l3e > bv) { bv = l3e; bx = vH + 1; }
            }
            pv[2 * bp] = bv; pi[2 * bp] = bx;
            bv = NEG_INF; bx = 0x7fffffff;
            if (vL < VOCAB) {
                if (l0o > bv) { bv = l0o; bx = vL; }
                if (l1o > bv) { bv = l1o; bx = vL + 1; }
            }
            if (vH < VOCAB) {
                if (l2o > bv) { bv = l2o; bx = vH; }
                if (l3o > bv) { bv = l3o; bx = vH + 1; }
            }
            pv[2 * bp + 1] = bv; pi[2 * bp + 1] = bx;
        }
#pragma unroll
        for (int s = 0; s < 8; s++) {
            float v = pv[s]; int ix = pi[s];
#pragma unroll
            for (int off = 16; off > 0; off >>= 1) {
                float ov = __shfl_xor_sync(0xffffffffu, v, off);
                int   oi = __shfl_xor_sync(0xffffffffu, ix, off);
                if (ov > v || (ov == v && oi < ix)) { v = ov; ix = oi; }
            }
            if (lane == 0) {
                g_pmax[bid * 64 + 8 * warp + s] = v;
                g_pidx[bid * 64 + 8 * warp + s] = ix;
            }
        }
    } else {
        // ================= attention block (h or c) ===========================
        const int a     = bid - NLOG;
        const int bi    = a & 63;
        const int which = a >> 6;
        const float* vr = (which ? g_crnn : g_hrnn) + (size_t)bi * HID;
        for (int d = tid; d < HID; d += 256) sm.a.vv[d] = vr[d];
        __syncthreads();
        for (int s = warp; s < SRC; s += 8) {
            float acc = 0.f;
            const float* er = enc + ((size_t)s * BATCH + bi) * HID;
            for (int d = lane; d < HID; d += 32) acc += er[d] * sm.a.vv[d];
#pragma unroll
            for (int o = 16; o > 0; o >>= 1) acc += __shfl_xor_sync(0xffffffffu, acc, o);
            if (lane == 0) sm.a.sc[s] = acc * 0.04419417382415922f; // 1/sqrt(512)
        }
        __syncthreads();
        if (tid == 0) {
            float m = sm.a.sc[0];
            for (int s = 1; s < SRC; s++) m = fmaxf(m, sm.a.sc[s]);
            float sum = 0.f;
            for (int s = 0; s < SRC; s++) { float e = expf(sm.a.sc[s] - m); sm.a.sc[s] = e; sum += e; }
            sm.a.isum = 1.f / sum;
        }
        __syncthreads();
        const float isum = sm.a.isum;
        float* dst = (which ? g_c : g_h) + (size_t)bi * HID;
        for (int d = tid; d < HID; d += 256) {
            float acc = 0.f;
#pragma unroll 10
            for (int s = 0; s < SRC; s++) acc += sm.a.sc[s] * enc[((size_t)s * BATCH + bi) * HID + d];
            dst[d] = acc * isum + sm.a.vv[d];
        }
    }

    // ================= last-block-done final argmax ===========================
    __threadfence();
    __syncthreads();
    if (tid == 0) {
        int old = atomicAdd(&g_done, 1);
        s_last = (old == (int)gridDim.x - 1);
    }
    __syncthreads();
    if (s_last) {
        const int b = tid & 63, grp = tid >> 6;
        float bv = NEG_INF; int bx = 0x7fffffff;
        for (int p = grp; p < NLOG; p += 4) {
            float v = g_pmax[p * 64 + b];
            int  ix = g_pidx[p * 64 + b];
            if (v > bv || (v == bv && ix < bx)) { bv = v; bx = ix; }
        }
        __syncthreads();   // all threads past union reuse of sm before writing sm.m
        sm.m.sv[tid] = bv; sm.m.si[tid] = bx;
        __syncthreads();
        if (tid < 64) {
            for (int g = 1; g < 4; g++) {
                float v = sm.m.sv[tid + 64 * g];
                int  ix = sm.m.si[tid + 64 * g];
                if (v > bv || (v == bv && ix < bx)) { bv = v; bx = ix; }
            }
            g_tok[b] = bx;
            if (write_tok) out_tok[b * STEPS + step] = (float)bx;
        }
        if (tid == 0) g_done = 0;
    }
}

// ---------------- launch: 1 init + 31 x (lstm, fused) -----------------------
extern "C" void kernel_launch(void* const* d_in, const int* in_sizes, int n_in,
                              void* d_out, int out_size) {
    const float* embed   = (const float*)d_in[0];
    const float* fc_bias = (const float*)d_in[1];
    const float* w_ih    = (const float*)d_in[2];
    const float* w_hh    = (const float*)d_in[3];
    const float* b_ih    = (const float*)d_in[4];
    const float* b_hh    = (const float*)d_in[5];
    const float* enc     = (const float*)d_in[6];
    const float* h0      = (const float*)d_in[7];
    const float* c0      = (const float*)d_in[8];
    const int*   t0      = (const int*)d_in[9];
    float* out = (float*)d_out;

    const long long LT = (long long)STEPS * BATCH * VOCAB;  // 99,200,000
    int write_tok = ((long long)out_size >= LT + (long long)BATCH * STEPS) ? 1 : 0;
    float* out_tok = out + LT;

    k_init<<<32, 256>>>(h0, c0, t0);
    for (int t = 0; t < STEPS; t++) {
        k_lstm<<<128, 512>>>(embed, w_ih, w_hh, b_ih, b_hh);
        k_fused<<<NLOG + 128, 256>>>(embed, fc_bias, enc,
                                     out + (long long)t * BATCH * VOCAB,
                                     out_tok, t, write_tok);
    }
}